// round 14
// baseline (speedup 1.0000x reference)
#include <cuda_runtime.h>

// Fused kernel. x-loads hoisted before the prelude barrier; 4 samples/thread,
// phase-strided (coalesced), grid 1024, __launch_bounds__(256,2).
//
// MUFU-diet: tanh reciprocal via 2-step FMA Newton. Domain fixed vs R13:
//   e = ex2(-|u|)  with u = 2*log2e*(W1.x+b1)   -> e in (0,1], d=1+e in [1,2]
//   tanh(|.|) = (1-e)*recip(d);  sign restored with copysignf(., u).
// MUFU per sample = 4 ex2 + 5 sin/cos = 9 (was 13 with rcp.approx).
//
// Math (verified rounds 2-3):
//   th_j = tanh_j + qw[0,j]
//   z    = K1*cos(th1)cos(th2)cos(th3) - K2*sin(th0)sin(th1)
//   out  = relu(z*W2 + b2) @ W3^T + b3

__global__ void __launch_bounds__(256, 2) qnn_fused(
    const float4* __restrict__ x4, float2* __restrict__ out, int stride,
    const float* __restrict__ W1, const float* __restrict__ b1,
    const float* __restrict__ qw, const float* __restrict__ W2,
    const float* __restrict__ b2, const float* __restrict__ W3,
    const float* __restrict__ b3)
{
    __shared__ float4 sc[11];

    const int i = blockIdx.x * blockDim.x + threadIdx.x;

    // ---- Front-batched sample loads, issued BEFORE the barrier. ----
    float4 xv0 = x4[i];
    float4 xv1 = x4[i + stride];
    float4 xv2 = x4[i + 2 * stride];
    float4 xv3 = x4[i + 3 * stride];

    {
        float* v = reinterpret_cast<float*>(sc);
        const float SC = 2.8853900817779268f;    // +2*log2(e): sign kept in u
        int t = threadIdx.x;
        if (t < 16)      v[t] = SC * W1[t];                 // W1s rows 0..3
        else if (t < 20) v[t] = SC * b1[t - 16];            // b1s
        else if (t < 24) v[t] = qw[t - 20];                 // qw[0,i]
        else if (t == 24) v[24] = __cosf(qw[8]);            // K1
        else if (t == 25) v[25] = __sinf(qw[8]) * __cosf(qw[4]) * __cosf(qw[5]); // K2
        else if (t < 28) v[t] = b3[t - 26];                 // b3
        else if (t < 32) v[t] = W2[t - 28];                 // W2
        else if (t < 36) v[t] = b2[t - 32];                 // b2
        else if (t < 44) v[t] = W3[t - 36];                 // W3 (2x4)
    }
    __syncthreads();

    const float4 r0 = sc[0], r1 = sc[1], r2 = sc[2], r3 = sc[3], bs = sc[4];
    const float4 q0 = sc[5], kk = sc[6];
    const float4 W2v = sc[7], b2v = sc[8], W3a = sc[9], W3b = sc[10];

    float4 xv[4] = {xv0, xv1, xv2, xv3};

    #pragma unroll
    for (int k = 0; k < 4; ++k) {
        float4 x = xv[k];

        // u_j = +2*log2e*(W1[j,:].x + b1[j]); sign(tanh) = sign(u)
        float u0 = fmaf(r0.x, x.x, fmaf(r0.y, x.y, fmaf(r0.z, x.z, fmaf(r0.w, x.w, bs.x))));
        float u1 = fmaf(r1.x, x.x, fmaf(r1.y, x.y, fmaf(r1.z, x.z, fmaf(r1.w, x.w, bs.y))));
        float u2 = fmaf(r2.x, x.x, fmaf(r2.y, x.y, fmaf(r2.z, x.z, fmaf(r2.w, x.w, bs.z))));
        float u3 = fmaf(r3.x, x.x, fmaf(r3.y, x.y, fmaf(r3.z, x.z, fmaf(r3.w, x.w, bs.w))));

        float e0, e1, e2, e3;
        float a0 = -fabsf(u0), a1 = -fabsf(u1), a2 = -fabsf(u2), a3 = -fabsf(u3);
        asm("ex2.approx.f32 %0, %1;" : "=f"(e0) : "f"(a0));
        asm("ex2.approx.f32 %0, %1;" : "=f"(e1) : "f"(a1));
        asm("ex2.approx.f32 %0, %1;" : "=f"(e2) : "f"(a2));
        asm("ex2.approx.f32 %0, %1;" : "=f"(e3) : "f"(a3));

        // FMA-only reciprocal of d = 1+e, e in (0,1] => d in [1,2].
        float d0 = 1.0f + e0, d1 = 1.0f + e1, d2 = 1.0f + e2, d3 = 1.0f + e3;
        float w0 = fmaf(-0.47058823529411764f, d0, 1.4117647058823530f);
        float w1 = fmaf(-0.47058823529411764f, d1, 1.4117647058823530f);
        float w2 = fmaf(-0.47058823529411764f, d2, 1.4117647058823530f);
        float w3 = fmaf(-0.47058823529411764f, d3, 1.4117647058823530f);
        w0 = w0 * fmaf(-d0, w0, 2.0f);  w0 = w0 * fmaf(-d0, w0, 2.0f);
        w1 = w1 * fmaf(-d1, w1, 2.0f);  w1 = w1 * fmaf(-d1, w1, 2.0f);
        w2 = w2 * fmaf(-d2, w2, 2.0f);  w2 = w2 * fmaf(-d2, w2, 2.0f);
        w3 = w3 * fmaf(-d3, w3, 2.0f);  w3 = w3 * fmaf(-d3, w3, 2.0f);

        // th = copysign((1-e)*w, u) + q
        float th0 = copysignf((1.0f - e0) * w0, u0) + q0.x;
        float th1 = copysignf((1.0f - e1) * w1, u1) + q0.y;
        float th2 = copysignf((1.0f - e2) * w2, u2) + q0.z;
        float th3 = copysignf((1.0f - e3) * w3, u3) + q0.w;

        float s0 = __sinf(th0);
        float s1 = __sinf(th1);
        float c1 = __cosf(th1);
        float c2 = __cosf(th2);
        float c3 = __cosf(th3);

        float z = fmaf(kk.x, c1 * c2 * c3, -kk.y * (s0 * s1));

        float h20 = fmaxf(fmaf(z, W2v.x, b2v.x), 0.f);
        float h21 = fmaxf(fmaf(z, W2v.y, b2v.y), 0.f);
        float h22 = fmaxf(fmaf(z, W2v.z, b2v.z), 0.f);
        float h23 = fmaxf(fmaf(z, W2v.w, b2v.w), 0.f);
        float o0 = fmaf(h20, W3a.x, fmaf(h21, W3a.y, fmaf(h22, W3a.z, fmaf(h23, W3a.w, kk.z))));
        float o1 = fmaf(h20, W3b.x, fmaf(h21, W3b.y, fmaf(h22, W3b.z, fmaf(h23, W3b.w, kk.w))));
        out[i + k * stride] = make_float2(o0, o1);
    }
}

extern "C" void kernel_launch(void* const* d_in, const int* in_sizes, int n_in,
                              void* d_out, int out_size) {
    const float* x  = (const float*)d_in[0];
    const float* W1 = (const float*)d_in[1];
    const float* b1 = (const float*)d_in[2];
    const float* qw = (const float*)d_in[3];
    const float* W2 = (const float*)d_in[4];
    const float* b2 = (const float*)d_in[5];
    const float* W3 = (const float*)d_in[6];
    const float* b3 = (const float*)d_in[7];

    int n = in_sizes[0] / 4;    // samples (1048576)
    int stride = n / 4;         // 4 samples per thread
    const int threads = 256;
    const int blocks = stride / threads;   // 1024
    qnn_fused<<<blocks, threads>>>((const float4*)x, (float2*)d_out, stride,
                                   W1, b1, qw, W2, b2, W3, b3);
}